// round 12
// baseline (speedup 1.0000x reference)
#include <cuda_runtime.h>
#include <cuda_bf16.h>
#include <cstdint>

#define T_LEN    8192
#define L_WIN    64
#define TP_LEN   (T_LEN - L_WIN + 1)   // 8129
#define P_NUM    64
#define BS       32
#define TILE_M   256
#define THREADS  512
#define PAD_LEFT 32
#define EPS      1e-6f

#define SA       72
#define SA_B     (SA * 2)                  // 144 B per B row
#define B_BYTES  (P_NUM * SA_B)            // 9216
#define DYN_SMEM B_BYTES

// precomputed z-normed shapelets (bf16, ldsm row layout [64][SA]) + s2
__device__ __nv_bfloat16 g_Bs[P_NUM * SA];
__device__ float         g_s2[P_NUM];

__device__ __forceinline__ uint32_t smem_u32(const void* p) {
    uint32_t a;
    asm("{ .reg .u64 t; cvta.to.shared.u64 t, %1; cvt.u32.u64 %0, t; }"
        : "=r"(a) : "l"(p));
    return a;
}

__device__ __forceinline__ void ldsm_x4(uint32_t& r0, uint32_t& r1,
                                        uint32_t& r2, uint32_t& r3, uint32_t addr) {
    asm volatile("ldmatrix.sync.aligned.m8n8.x4.shared.b16 {%0,%1,%2,%3}, [%4];"
                 : "=r"(r0), "=r"(r1), "=r"(r2), "=r"(r3) : "r"(addr));
}

__device__ __forceinline__ void mma_16816_bf16(
    float* c, uint32_t a0, uint32_t a1, uint32_t a2, uint32_t a3,
    uint32_t b0, uint32_t b1)
{
    asm volatile(
        "mma.sync.aligned.m16n8k16.row.col.f32.bf16.bf16.f32 "
        "{%0,%1,%2,%3}, {%4,%5,%6,%7}, {%8,%9}, {%0,%1,%2,%3};"
        : "+f"(c[0]), "+f"(c[1]), "+f"(c[2]), "+f"(c[3])
        : "r"(a0), "r"(a1), "r"(a2), "r"(a3), "r"(b0), "r"(b1));
}

// ---------------------------------------------------------------------------
// Prep: z-normalize shapelets once; write bf16 B-tile (ldsm layout) + s2.
// ---------------------------------------------------------------------------
__global__ void __launch_bounds__(256)
prep_shapelets(const float* __restrict__ sh) {
    const int lane = threadIdx.x & 31;
    const int wrp  = threadIdx.x >> 5;
    #pragma unroll
    for (int i = 0; i < 8; i++) {
        const int r = wrp * 8 + i;
        float v0 = sh[r * 64 + lane];
        float v1 = sh[r * 64 + lane + 32];
        float a = v0 + v1;
        float c = fmaf(v0, v0, v1 * v1);
        #pragma unroll
        for (int m = 16; m > 0; m >>= 1) {
            a += __shfl_xor_sync(0xffffffffu, a, m);
            c += __shfl_xor_sync(0xffffffffu, c, m);
        }
        float mu  = a * (1.f / L_WIN);
        float var = fmaxf(c * (1.f / L_WIN) - mu * mu, 0.f);
        float inv = 1.f / fmaxf(sqrtf(var), EPS);
        g_Bs[r * SA + lane]      = __float2bfloat16((v0 - mu) * inv);
        g_Bs[r * SA + lane + 32] = __float2bfloat16((v1 - mu) * inv);
        if (lane == 0) g_s2[r] = var * inv * inv * (float)L_WIN;
    }
}

// ---------------------------------------------------------------------------
// Main: 256 windows x 64 shapelets per CTA (512 thr, 16 warps, warp = 16
// rows). A-fragments direct from bf16x2 shift replicas; B via ldsm.
// act = exp(2*inv_t*dot - w2_t - s2_p). Shfl pair-exchange -> STG.128.
// ---------------------------------------------------------------------------
__global__ void __launch_bounds__(THREADS, 2)
shapelet_hmma8_kernel(const float* __restrict__ x,
                      const float* __restrict__ sh,
                      float* __restrict__ out)
{
    extern __shared__ char dyn[];   // B tile only (ldsm layout)

    __shared__ float    xs[324];              // 320 + zero pad
    __shared__ float    E1[324], E2[324];     // exclusive prefix sums
    __shared__ uint32_t xe[160], xo[160];     // bf16x2 replicas (even/odd)
    __shared__ float    invs[TILE_M], w2s[TILE_M], s2s[P_NUM];
    __shared__ float    ws1[16], ws2[16];

    const int tid  = threadIdx.x;
    const int lane = tid & 31;
    const int wrp  = tid >> 5;                // 0..15
    const int b    = blockIdx.y;
    const int t0   = blockIdx.x * TILE_M;

    // ---- loads: x segment (320) + precomputed B tile + s2 ----
    {
        const float* xb = x + (size_t)b * T_LEN;
        if (tid < 324) {
            float v = 0.f;
            if (tid < 320) {
                int i0 = t0 + tid;
                v = (i0 < T_LEN) ? xb[i0] : 0.f;
            }
            xs[tid] = v;
        }
        const uint4* gB = reinterpret_cast<const uint4*>(g_Bs);
        uint4*       sB = reinterpret_cast<uint4*>(dyn);
        sB[tid % (B_BYTES / 16)] = gB[tid % (B_BYTES / 16)];
        int idx2 = tid + THREADS;
        if (idx2 < (B_BYTES / 16)) sB[idx2] = gB[idx2];
        if (tid < P_NUM) s2s[tid] = g_s2[tid];
    }
    __syncthreads();

    // ---- prefix scan of x, x^2 over 320 entries (warps 0..9) ----
    float s1 = 0.f, sq = 0.f;
    if (tid < 320) {
        float v = xs[tid];
        s1 = v; sq = v * v;
        #pragma unroll
        for (int m = 1; m < 32; m <<= 1) {
            float a = __shfl_up_sync(0xffffffffu, s1, m);
            float c = __shfl_up_sync(0xffffffffu, sq, m);
            if (lane >= m) { s1 += a; sq += c; }
        }
        if (lane == 31) { ws1[wrp] = s1; ws2[wrp] = sq; }
    }
    // bf16x2 replicas (independent of scan)
    if (tid < 160) {
        float a0 = xs[2 * tid], a1 = xs[2 * tid + 1], a2 = xs[2 * tid + 2];
        __nv_bfloat162 he = __floats2bfloat162_rn(a0, a1);
        __nv_bfloat162 ho = __floats2bfloat162_rn(a1, a2);
        xe[tid] = *reinterpret_cast<uint32_t*>(&he);
        xo[tid] = *reinterpret_cast<uint32_t*>(&ho);
    }
    __syncthreads();
    if (tid < 32) {
        float a = (lane < 10) ? ws1[lane] : 0.f;
        float c = (lane < 10) ? ws2[lane] : 0.f;
        #pragma unroll
        for (int m = 1; m < 16; m <<= 1) {
            float ta = __shfl_up_sync(0xffffffffu, a, m);
            float tc = __shfl_up_sync(0xffffffffu, c, m);
            if (lane >= m) { a += ta; c += tc; }
        }
        float ae = __shfl_up_sync(0xffffffffu, a, 1);
        float ce = __shfl_up_sync(0xffffffffu, c, 1);
        if (lane == 0) { ae = 0.f; ce = 0.f; }
        if (lane < 10) { ws1[lane] = ae; ws2[lane] = ce; }
    }
    __syncthreads();
    if (tid < 320) {
        E1[tid + 1] = s1 + ws1[wrp];
        E2[tid + 1] = sq + ws2[wrp];
    }
    if (tid == 0) { E1[0] = 0.f; E2[0] = 0.f; }
    __syncthreads();

    // ---- window stats from prefix sums (threads 0..255) ----
    if (tid < TILE_M) {
        float a1 = E1[tid + 64] - E1[tid];
        float a2 = E2[tid + 64] - E2[tid];
        float mu  = a1 * (1.f / L_WIN);
        float var = fmaxf(a2 * (1.f / L_WIN) - mu * mu, 0.f);
        float inv = 1.f / fmaxf(sqrtf(var), EPS);
        invs[tid] = inv;
        w2s[tid]  = var * inv * inv * (float)L_WIN;
    }
    __syncthreads();

    // ---- A fragments directly from replicas ----
    // s0 = wrp*16 + g + tq*2; pair j = {x[s0+8j], x[s0+8j+1]}.
    // a0(k)=xw[2k], a1=a2=xw[2k+1], a3=xw[2k+2].
    const int g  = lane >> 2;
    const int tq = lane & 3;
    uint32_t xw[9];
    {
        const int s0 = wrp * 16 + g + tq * 2;
        const uint32_t* src = (s0 & 1) ? xo : xe;
        const int w0 = s0 >> 1;
        #pragma unroll
        for (int j = 0; j < 9; j++) xw[j] = src[w0 + 4 * j];
    }

    // ---- B fragments via ldsm + MMA (warp owns rows 16*wrp..+15) ----
    const int rr = lane & 7;
    const int q  = lane >> 3;
    const uint32_t Bu = smem_u32(dyn);
    const uint32_t bAddr = Bu + (uint32_t)(rr + (q >> 1) * 8) * SA_B
                              + (uint32_t)(q & 1) * 16;

    float c[8][4];
    #pragma unroll
    for (int nt = 0; nt < 8; nt++)
        #pragma unroll
        for (int r = 0; r < 4; r++) c[nt][r] = 0.f;

    #pragma unroll
    for (int k = 0; k < 4; k++) {
        const uint32_t a0 = xw[2 * k], a12 = xw[2 * k + 1], a3 = xw[2 * k + 2];
        #pragma unroll
        for (int nt2 = 0; nt2 < 4; nt2++) {
            uint32_t b0, b1, b2, b3;
            ldsm_x4(b0, b1, b2, b3,
                    bAddr + (uint32_t)nt2 * (16 * SA_B) + (uint32_t)k * 32);
            mma_16816_bf16(c[2 * nt2],     a0, a12, a12, a3, b0, b1);
            mma_16816_bf16(c[2 * nt2 + 1], a0, a12, a12, a3, b2, b3);
        }
    }

    // ---- epilogue: exp, shfl pair-exchange, STG.128 ----
    {
        float* outb = out + (size_t)b * T_LEN * P_NUM;
        #pragma unroll
        for (int half = 0; half < 2; half++) {
            const int rowL = wrp * 16 + g + half * 8;
            const int tout = t0 + rowL + PAD_LEFT;
            const bool ok  = (t0 + rowL) < TP_LEN;
            const float inv2 = 2.f * invs[rowL];
            const float cw   = w2s[rowL];
            float2 e[8];
            #pragma unroll
            for (int nt = 0; nt < 8; nt++) {
                const int col = nt * 8 + tq * 2;
                e[nt].x = ok ? __expf(fmaf(inv2, c[nt][half * 2 + 0], -(cw + s2s[col])))     : 0.f;
                e[nt].y = ok ? __expf(fmaf(inv2, c[nt][half * 2 + 1], -(cw + s2s[col + 1]))) : 0.f;
            }
            float* orow = outb + (size_t)tout * P_NUM;
            #pragma unroll
            for (int j = 0; j < 4; j++) {
                const int nt0 = 2 * j, nt1 = 2 * j + 1;
                float2 send = (tq & 1) ? e[nt0] : e[nt1];
                long long sl; memcpy(&sl, &send, 8);
                long long rl = __shfl_xor_sync(0xffffffffu, sl, 1);
                float2 recv; memcpy(&recv, &rl, 8);
                float2 own = (tq & 1) ? e[nt1] : e[nt0];
                float4 v = (tq & 1)
                    ? make_float4(recv.x, recv.y, own.x, own.y)
                    : make_float4(own.x, own.y, recv.x, recv.y);
                const int col = ((tq & 1) ? nt1 : nt0) * 8 + (tq & 2) * 2;
                if (tout < T_LEN)
                    *reinterpret_cast<float4*>(orow + col) = v;
            }
        }
        // left pad rows [0,32): zeros (tile 0 only)
        if (blockIdx.x == 0) {
            int row = tid >> 4;
            int c4  = tid & 15;
            if (row < PAD_LEFT) {
                float4 z = make_float4(0.f, 0.f, 0.f, 0.f);
                *reinterpret_cast<float4*>(outb + (size_t)row * P_NUM + c4 * 4) = z;
            }
        }
    }
}

extern "C" void kernel_launch(void* const* d_in, const int* in_sizes, int n_in,
                              void* d_out, int out_size) {
    const float* x  = (const float*)d_in[0];   // (32, 8192, 1)
    const float* sh = (const float*)d_in[1];   // (64, 1, 64)
    float* out = (float*)d_out;                // (32, 8192, 64)

    prep_shapelets<<<1, 256>>>(sh);

    cudaFuncSetAttribute(shapelet_hmma8_kernel,
                         cudaFuncAttributeMaxDynamicSharedMemorySize, DYN_SMEM);
    dim3 grid((TP_LEN + TILE_M - 1) / TILE_M, BS);   // (32, 32)
    shapelet_hmma8_kernel<<<grid, THREADS, DYN_SMEM>>>(x, sh, out);
}

// round 13
// speedup vs baseline: 1.1318x; 1.1318x over previous
#include <cuda_runtime.h>
#include <cuda_bf16.h>
#include <cstdint>

#define T_LEN    8192
#define L_WIN    64
#define TP_LEN   (T_LEN - L_WIN + 1)   // 8129
#define P_NUM    64
#define BS       32
#define TILE_M   128
#define PAD_LEFT 32
#define EPS      1e-6f

#define SA       72
#define SA_B     (SA * 2)                  // 144 B per B row
#define B_BYTES  (P_NUM * SA_B)            // 9216
#define DYN_SMEM B_BYTES

// precomputed z-normed shapelets (bf16, ldsm row layout [64][SA])
__device__ __nv_bfloat16 g_Bs[P_NUM * SA];

__device__ __forceinline__ uint32_t smem_u32(const void* p) {
    uint32_t a;
    asm("{ .reg .u64 t; cvta.to.shared.u64 t, %1; cvt.u32.u64 %0, t; }"
        : "=r"(a) : "l"(p));
    return a;
}

__device__ __forceinline__ void ldsm_x4(uint32_t& r0, uint32_t& r1,
                                        uint32_t& r2, uint32_t& r3, uint32_t addr) {
    asm volatile("ldmatrix.sync.aligned.m8n8.x4.shared.b16 {%0,%1,%2,%3}, [%4];"
                 : "=r"(r0), "=r"(r1), "=r"(r2), "=r"(r3) : "r"(addr));
}

__device__ __forceinline__ void mma_16816_bf16(
    float* c, uint32_t a0, uint32_t a1, uint32_t a2, uint32_t a3,
    uint32_t b0, uint32_t b1)
{
    asm volatile(
        "mma.sync.aligned.m16n8k16.row.col.f32.bf16.bf16.f32 "
        "{%0,%1,%2,%3}, {%4,%5,%6,%7}, {%8,%9}, {%0,%1,%2,%3};"
        : "+f"(c[0]), "+f"(c[1]), "+f"(c[2]), "+f"(c[3])
        : "r"(a0), "r"(a1), "r"(a2), "r"(a3), "r"(b0), "r"(b1));
}

// ---------------------------------------------------------------------------
// Prep: z-normalize shapelets once; write bf16 B-tile (ldsm layout).
// Signals PDL dependents as soon as its work is done.
// ---------------------------------------------------------------------------
__global__ void __launch_bounds__(256)
prep_shapelets(const float* __restrict__ sh) {
    const int lane = threadIdx.x & 31;
    const int wrp  = threadIdx.x >> 5;
    #pragma unroll
    for (int i = 0; i < 8; i++) {
        const int r = wrp * 8 + i;
        float v0 = sh[r * 64 + lane];
        float v1 = sh[r * 64 + lane + 32];
        float a = v0 + v1;
        float c = fmaf(v0, v0, v1 * v1);
        #pragma unroll
        for (int m = 16; m > 0; m >>= 1) {
            a += __shfl_xor_sync(0xffffffffu, a, m);
            c += __shfl_xor_sync(0xffffffffu, c, m);
        }
        float mu  = a * (1.f / L_WIN);
        float var = fmaxf(c * (1.f / L_WIN) - mu * mu, 0.f);
        float inv = 1.f / fmaxf(sqrtf(var), EPS);
        g_Bs[r * SA + lane]      = __float2bfloat16((v0 - mu) * inv);
        g_Bs[r * SA + lane + 32] = __float2bfloat16((v1 - mu) * inv);
    }
    asm volatile("griddepcontrol.launch_dependents;" ::: "memory");
}

// ---------------------------------------------------------------------------
// Main: 128 windows x 64 shapelets per CTA; A-fragments from bf16x2 shift
// replicas (a1==a2, a3(k)==a0(k+1)); B via ldsm from precomputed tile.
// w2 == s2 == 64 identically -> act = exp(2*inv_t*dot - 128).
// ---------------------------------------------------------------------------
__global__ void __launch_bounds__(256)
shapelet_hmma9_kernel(const float* __restrict__ x,
                      const float* __restrict__ sh,
                      float* __restrict__ out)
{
    extern __shared__ char dyn[];   // B tile only (ldsm layout)

    __shared__ float    xs[258];              // 192 real + zero pad
    __shared__ float    E1[260], E2[260];     // exclusive prefix sums
    __shared__ uint32_t xe[96], xo[96];       // bf16x2 replicas (even/odd)
    __shared__ float    invs[TILE_M];
    __shared__ float    ws1[8], ws2[8];

    const int tid  = threadIdx.x;
    const int lane = tid & 31;
    const int wrp  = tid >> 5;
    const int b    = blockIdx.y;
    const int t0   = blockIdx.x * TILE_M;

    // ---- x segment load (independent of prep kernel) ----
    {
        const float* xb = x + (size_t)b * T_LEN;
        float v = 0.f;
        if (tid < 192) {
            int i0 = t0 + tid;
            v = (i0 < T_LEN) ? xb[i0] : 0.f;
        }
        xs[tid] = v;
    }
    __syncthreads();

    // ---- prefix scan of x, x^2 over 256 entries ----
    float s1, sq;
    {
        float v = xs[tid];
        s1 = v; sq = v * v;
        #pragma unroll
        for (int m = 1; m < 32; m <<= 1) {
            float a = __shfl_up_sync(0xffffffffu, s1, m);
            float c = __shfl_up_sync(0xffffffffu, sq, m);
            if (lane >= m) { s1 += a; sq += c; }
        }
        if (lane == 31) { ws1[wrp] = s1; ws2[wrp] = sq; }
    }
    // bf16x2 replicas (independent of scan)
    if (tid < 96) {
        float a0 = xs[2 * tid], a1 = xs[2 * tid + 1], a2 = xs[2 * tid + 2];
        __nv_bfloat162 he = __floats2bfloat162_rn(a0, a1);
        __nv_bfloat162 ho = __floats2bfloat162_rn(a1, a2);
        xe[tid] = *reinterpret_cast<uint32_t*>(&he);
        xo[tid] = *reinterpret_cast<uint32_t*>(&ho);
    }
    __syncthreads();
    if (tid < 32) {
        float a = (lane < 8) ? ws1[lane] : 0.f;
        float c = (lane < 8) ? ws2[lane] : 0.f;
        #pragma unroll
        for (int m = 1; m < 8; m <<= 1) {
            float ta = __shfl_up_sync(0xffffffffu, a, m);
            float tc = __shfl_up_sync(0xffffffffu, c, m);
            if (lane >= m) { a += ta; c += tc; }
        }
        float ae = __shfl_up_sync(0xffffffffu, a, 1);
        float ce = __shfl_up_sync(0xffffffffu, c, 1);
        if (lane == 0) { ae = 0.f; ce = 0.f; }
        if (lane < 8) { ws1[lane] = ae; ws2[lane] = ce; }
    }
    __syncthreads();
    E1[tid + 1] = s1 + ws1[wrp];
    E2[tid + 1] = sq + ws2[wrp];
    if (tid == 0) { E1[0] = 0.f; E2[0] = 0.f; }
    __syncthreads();

    // ---- window inv from prefix sums (threads 0..127) ----
    if (tid < TILE_M) {
        float a1 = E1[tid + 64] - E1[tid];
        float a2 = E2[tid + 64] - E2[tid];
        float mu  = a1 * (1.f / L_WIN);
        float var = fmaxf(a2 * (1.f / L_WIN) - mu * mu, 0.f);
        invs[tid] = 1.f / fmaxf(sqrtf(var), EPS);
    }

    // ---- wait for prep kernel results, then copy B tile ----
    asm volatile("griddepcontrol.wait;" ::: "memory");
    {
        const uint4* gB = reinterpret_cast<const uint4*>(g_Bs);
        uint4*       sB = reinterpret_cast<uint4*>(dyn);
        #pragma unroll
        for (int i = 0; i < 3; i++) {
            int idx = tid + i * 256;
            if (idx < (B_BYTES / 16)) sB[idx] = gB[idx];
        }
    }
    __syncthreads();

    // ---- A fragments directly from replicas ----
    const int g  = lane >> 2;
    const int tq = lane & 3;
    uint32_t xw[9];
    {
        const int s0 = wrp * 16 + g + tq * 2;
        const uint32_t* src = (s0 & 1) ? xo : xe;
        const int w0 = s0 >> 1;
        #pragma unroll
        for (int j = 0; j < 9; j++) xw[j] = src[w0 + 4 * j];
    }

    // ---- B fragments via ldsm + MMA (warp owns rows 16*wrp..+15) ----
    const int rr = lane & 7;
    const int q  = lane >> 3;
    const uint32_t Bu = smem_u32(dyn);
    const uint32_t bAddr = Bu + (uint32_t)(rr + (q >> 1) * 8) * SA_B
                              + (uint32_t)(q & 1) * 16;

    float c[8][4];
    #pragma unroll
    for (int nt = 0; nt < 8; nt++)
        #pragma unroll
        for (int r = 0; r < 4; r++) c[nt][r] = 0.f;

    #pragma unroll
    for (int k = 0; k < 4; k++) {
        const uint32_t a0 = xw[2 * k], a12 = xw[2 * k + 1], a3 = xw[2 * k + 2];
        #pragma unroll
        for (int nt2 = 0; nt2 < 4; nt2++) {
            uint32_t b0, b1, b2, b3;
            ldsm_x4(b0, b1, b2, b3,
                    bAddr + (uint32_t)nt2 * (16 * SA_B) + (uint32_t)k * 32);
            mma_16816_bf16(c[2 * nt2],     a0, a12, a12, a3, b0, b1);
            mma_16816_bf16(c[2 * nt2 + 1], a0, a12, a12, a3, b2, b3);
        }
    }

    // ---- epilogue: act = exp(2*inv*dot - 128); shfl pair-exchange; STG.128 ----
    {
        float* outb = out + (size_t)b * T_LEN * P_NUM;
        #pragma unroll
        for (int half = 0; half < 2; half++) {
            const int rowL = wrp * 16 + g + half * 8;
            const int tout = t0 + rowL + PAD_LEFT;
            const bool ok  = (t0 + rowL) < TP_LEN;
            const float inv2 = 2.f * invs[rowL];
            float2 e[8];
            #pragma unroll
            for (int nt = 0; nt < 8; nt++) {
                e[nt].x = ok ? __expf(fmaf(inv2, c[nt][half * 2 + 0], -128.f)) : 0.f;
                e[nt].y = ok ? __expf(fmaf(inv2, c[nt][half * 2 + 1], -128.f)) : 0.f;
            }
            float* orow = outb + (size_t)tout * P_NUM;
            #pragma unroll
            for (int j = 0; j < 4; j++) {
                const int nt0 = 2 * j, nt1 = 2 * j + 1;
                float2 send = (tq & 1) ? e[nt0] : e[nt1];
                long long sl; memcpy(&sl, &send, 8);
                long long rl = __shfl_xor_sync(0xffffffffu, sl, 1);
                float2 recv; memcpy(&recv, &rl, 8);
                float2 own = (tq & 1) ? e[nt1] : e[nt0];
                float4 v = (tq & 1)
                    ? make_float4(recv.x, recv.y, own.x, own.y)
                    : make_float4(own.x, own.y, recv.x, recv.y);
                const int col = ((tq & 1) ? nt1 : nt0) * 8 + (tq & 2) * 2;
                if (tout < T_LEN)
                    *reinterpret_cast<float4*>(orow + col) = v;
            }
        }
        // left pad rows [0,32): zeros (tile 0 only)
        if (blockIdx.x == 0) {
            float4 z = make_float4(0.f, 0.f, 0.f, 0.f);
            #pragma unroll
            for (int it = 0; it < 2; it++) {
                int qq  = tid + it * 256;
                int row = qq >> 4;
                int c4  = qq & 15;
                *reinterpret_cast<float4*>(outb + (size_t)row * P_NUM + c4 * 4) = z;
            }
        }
    }
}

extern "C" void kernel_launch(void* const* d_in, const int* in_sizes, int n_in,
                              void* d_out, int out_size) {
    const float* x  = (const float*)d_in[0];   // (32, 8192, 1)
    const float* sh = (const float*)d_in[1];   // (64, 1, 64)
    float* out = (float*)d_out;                // (32, 8192, 64)

    prep_shapelets<<<1, 256>>>(sh);

    cudaFuncSetAttribute(shapelet_hmma9_kernel,
                         cudaFuncAttributeMaxDynamicSharedMemorySize, DYN_SMEM);

    cudaLaunchAttribute attrs[1];
    attrs[0].id = cudaLaunchAttributeProgrammaticStreamSerialization;
    attrs[0].val.programmaticStreamSerializationAllowed = 1;

    cudaLaunchConfig_t cfg = {};
    cfg.gridDim  = dim3((TP_LEN + TILE_M - 1) / TILE_M, BS);   // (64, 32)
    cfg.blockDim = dim3(256, 1, 1);
    cfg.dynamicSmemBytes = DYN_SMEM;
    cfg.attrs    = attrs;
    cfg.numAttrs = 1;
    cudaLaunchKernelEx(&cfg, shapelet_hmma9_kernel, x, sh, out);
}

// round 14
// speedup vs baseline: 1.2270x; 1.0842x over previous
#include <cuda_runtime.h>
#include <cuda_bf16.h>
#include <cstdint>
#include <math_constants.h>

#define T_LEN    8192
#define L_WIN    64
#define TP_LEN   (T_LEN - L_WIN + 1)   // 8129
#define P_NUM    64
#define BS       32
#define TILE_M   128
#define PAD_LEFT 32
#define EPS      1e-6f
#define LOG2E    1.4426950408889634f

#define SA       72
#define SA_B     (SA * 2)                  // 144 B per B row
#define B_BYTES  (P_NUM * SA_B)            // 9216
#define DYN_SMEM B_BYTES

#define STAT_TILE 256                       // windows per stats CTA
#define N_STAT    (BS * 32)                 // 1024 stats CTAs (32 tiles x 32 b)

// precomputed: z-normed shapelets (bf16 ldsm layout) + per-window 1/std
__device__ __nv_bfloat16 g_Bs[P_NUM * SA];
__device__ float         g_invs[BS * T_LEN];   // 1 MB scratch

__device__ __forceinline__ uint32_t smem_u32(const void* p) {
    uint32_t a;
    asm("{ .reg .u64 t; cvta.to.shared.u64 t, %1; cvt.u32.u64 %0, t; }"
        : "=r"(a) : "l"(p));
    return a;
}
__device__ __forceinline__ float ex2f(float v) {
    float r;
    asm("ex2.approx.f32 %0, %1;" : "=f"(r) : "f"(v));
    return r;
}
__device__ __forceinline__ void ldsm_x4(uint32_t& r0, uint32_t& r1,
                                        uint32_t& r2, uint32_t& r3, uint32_t addr) {
    asm volatile("ldmatrix.sync.aligned.m8n8.x4.shared.b16 {%0,%1,%2,%3}, [%4];"
                 : "=r"(r0), "=r"(r1), "=r"(r2), "=r"(r3) : "r"(addr));
}
__device__ __forceinline__ void mma_16816_bf16(
    float* c, uint32_t a0, uint32_t a1, uint32_t a2, uint32_t a3,
    uint32_t b0, uint32_t b1)
{
    asm volatile(
        "mma.sync.aligned.m16n8k16.row.col.f32.bf16.bf16.f32 "
        "{%0,%1,%2,%3}, {%4,%5,%6,%7}, {%8,%9}, {%0,%1,%2,%3};"
        : "+f"(c[0]), "+f"(c[1]), "+f"(c[2]), "+f"(c[3])
        : "r"(a0), "r"(a1), "r"(a2), "r"(a3), "r"(b0), "r"(b1));
}

// ---------------------------------------------------------------------------
// Prep: CTAs 0..1023 compute window inv_t (prefix-scan over 320 x values);
// CTA 1024 z-normalizes shapelets into g_Bs. PDL-signals when done.
// ---------------------------------------------------------------------------
__global__ void __launch_bounds__(320)
prep_kernel(const float* __restrict__ x, const float* __restrict__ sh) {
    const int tid  = threadIdx.x;
    const int lane = tid & 31;
    const int wrp  = tid >> 5;          // 0..9
    const int id   = blockIdx.x;

    if (id == N_STAT) {
        // shapelet z-norm (warps 0..7, 8 rows each)
        if (wrp < 8) {
            #pragma unroll
            for (int i = 0; i < 8; i++) {
                const int r = wrp * 8 + i;
                float v0 = sh[r * 64 + lane];
                float v1 = sh[r * 64 + lane + 32];
                float a = v0 + v1;
                float c = fmaf(v0, v0, v1 * v1);
                #pragma unroll
                for (int m = 16; m > 0; m >>= 1) {
                    a += __shfl_xor_sync(0xffffffffu, a, m);
                    c += __shfl_xor_sync(0xffffffffu, c, m);
                }
                float mu  = a * (1.f / L_WIN);
                float var = fmaxf(c * (1.f / L_WIN) - mu * mu, 0.f);
                float inv = 1.f / fmaxf(sqrtf(var), EPS);
                g_Bs[r * SA + lane]      = __float2bfloat16((v0 - mu) * inv);
                g_Bs[r * SA + lane + 32] = __float2bfloat16((v1 - mu) * inv);
            }
        }
    } else {
        __shared__ float xs[324], E1[324], E2[324];
        __shared__ float ws1[16], ws2[16];
        const int b  = id >> 5;
        const int t0 = (id & 31) * STAT_TILE;

        const float* xb = x + (size_t)b * T_LEN;
        {
            int i0 = t0 + tid;
            xs[tid] = (i0 < T_LEN) ? xb[i0] : 0.f;
            if (tid < 4) xs[320 + tid] = 0.f;
        }
        __syncthreads();

        float s1, sq;
        {
            float v = xs[tid];
            s1 = v; sq = v * v;
            #pragma unroll
            for (int m = 1; m < 32; m <<= 1) {
                float a = __shfl_up_sync(0xffffffffu, s1, m);
                float c = __shfl_up_sync(0xffffffffu, sq, m);
                if (lane >= m) { s1 += a; sq += c; }
            }
            if (lane == 31) { ws1[wrp] = s1; ws2[wrp] = sq; }
        }
        __syncthreads();
        if (tid < 32) {
            float a = (lane < 10) ? ws1[lane] : 0.f;
            float c = (lane < 10) ? ws2[lane] : 0.f;
            #pragma unroll
            for (int m = 1; m < 16; m <<= 1) {
                float ta = __shfl_up_sync(0xffffffffu, a, m);
                float tc = __shfl_up_sync(0xffffffffu, c, m);
                if (lane >= m) { a += ta; c += tc; }
            }
            float ae = __shfl_up_sync(0xffffffffu, a, 1);
            float ce = __shfl_up_sync(0xffffffffu, c, 1);
            if (lane == 0) { ae = 0.f; ce = 0.f; }
            if (lane < 10) { ws1[lane] = ae; ws2[lane] = ce; }
        }
        __syncthreads();
        E1[tid + 1] = s1 + ws1[wrp];
        E2[tid + 1] = sq + ws2[wrp];
        if (tid == 0) { E1[0] = 0.f; E2[0] = 0.f; }
        __syncthreads();

        if (tid < STAT_TILE) {
            float a1 = E1[tid + 64] - E1[tid];
            float a2 = E2[tid + 64] - E2[tid];
            float mu  = a1 * (1.f / L_WIN);
            float var = fmaxf(a2 * (1.f / L_WIN) - mu * mu, 0.f);
            g_invs[b * T_LEN + t0 + tid] = 1.f / fmaxf(sqrtf(var), EPS);
        }
    }
    asm volatile("griddepcontrol.launch_dependents;" ::: "memory");
}

// ---------------------------------------------------------------------------
// Main: 128 windows x 64 shapelets per CTA. A-fragments from bf16x2 shift
// replicas; B via ldsm from precomputed tile; inv_t precomputed.
// act = exp2(2*inv*log2e*dot - 128*log2e). Shfl pair-exchange -> STG.128.
// ---------------------------------------------------------------------------
__global__ void __launch_bounds__(256)
shapelet_hmma10_kernel(const float* __restrict__ x,
                       const float* __restrict__ sh,
                       float* __restrict__ out)
{
    extern __shared__ char dyn[];   // B tile (ldsm layout)

    __shared__ float    xs[194];
    __shared__ uint32_t xe[96], xo[96];   // bf16x2 replicas (even/odd)
    __shared__ float    invs_s[TILE_M];

    const int tid  = threadIdx.x;
    const int lane = tid & 31;
    const int wrp  = tid >> 5;
    const int b    = blockIdx.y;
    const int t0   = blockIdx.x * TILE_M;

    // ---- x segment load (independent of prep kernel) ----
    {
        const float* xb = x + (size_t)b * T_LEN;
        if (tid < 194) {
            float v = 0.f;
            if (tid < 192) {
                int i0 = t0 + tid;
                v = (i0 < T_LEN) ? xb[i0] : 0.f;
            }
            xs[tid] = v;
        }
    }
    __syncthreads();

    // ---- bf16x2 replicas ----
    if (tid < 96) {
        float a0 = xs[2 * tid], a1 = xs[2 * tid + 1], a2 = xs[2 * tid + 2];
        __nv_bfloat162 he = __floats2bfloat162_rn(a0, a1);
        __nv_bfloat162 ho = __floats2bfloat162_rn(a1, a2);
        xe[tid] = *reinterpret_cast<uint32_t*>(&he);
        xo[tid] = *reinterpret_cast<uint32_t*>(&ho);
    }

    // ---- wait for prep; copy B tile + load invs ----
    asm volatile("griddepcontrol.wait;" ::: "memory");
    {
        const uint4* gB = reinterpret_cast<const uint4*>(g_Bs);
        uint4*       sB = reinterpret_cast<uint4*>(dyn);
        #pragma unroll
        for (int i = 0; i < 3; i++) {
            int idx = tid + i * 256;
            if (idx < (B_BYTES / 16)) sB[idx] = gB[idx];
        }
        if (tid < TILE_M) invs_s[tid] = g_invs[b * T_LEN + t0 + tid];
    }
    __syncthreads();

    // ---- A fragments directly from replicas ----
    const int g  = lane >> 2;
    const int tq = lane & 3;
    uint32_t xw[9];
    {
        const int s0 = wrp * 16 + g + tq * 2;
        const uint32_t* src = (s0 & 1) ? xo : xe;
        const int w0 = s0 >> 1;
        #pragma unroll
        for (int j = 0; j < 9; j++) xw[j] = src[w0 + 4 * j];
    }

    // ---- B fragments via ldsm + MMA (warp owns rows 16*wrp..+15) ----
    const int rr = lane & 7;
    const int q  = lane >> 3;
    const uint32_t Bu = smem_u32(dyn);
    const uint32_t bAddr = Bu + (uint32_t)(rr + (q >> 1) * 8) * SA_B
                              + (uint32_t)(q & 1) * 16;

    float c[8][4];
    #pragma unroll
    for (int nt = 0; nt < 8; nt++)
        #pragma unroll
        for (int r = 0; r < 4; r++) c[nt][r] = 0.f;

    #pragma unroll
    for (int k = 0; k < 4; k++) {
        const uint32_t a0 = xw[2 * k], a12 = xw[2 * k + 1], a3 = xw[2 * k + 2];
        #pragma unroll
        for (int nt2 = 0; nt2 < 4; nt2++) {
            uint32_t b0, b1, b2, b3;
            ldsm_x4(b0, b1, b2, b3,
                    bAddr + (uint32_t)nt2 * (16 * SA_B) + (uint32_t)k * 32);
            mma_16816_bf16(c[2 * nt2],     a0, a12, a12, a3, b0, b1);
            mma_16816_bf16(c[2 * nt2 + 1], a0, a12, a12, a3, b2, b3);
        }
    }

    // ---- epilogue: act = ex2(m*dot + cst); shfl pair-exchange; STG.128 ----
    {
        float* outb = out + (size_t)b * T_LEN * P_NUM;
        #pragma unroll
        for (int half = 0; half < 2; half++) {
            const int rowL = wrp * 16 + g + half * 8;
            const int tout = t0 + rowL + PAD_LEFT;
            const bool ok  = (t0 + rowL) < TP_LEN;
            const float m   = ok ? invs_s[rowL] * (2.f * LOG2E) : 0.f;
            const float cst = ok ? (-128.f * LOG2E) : -CUDART_INF_F;
            float2 e[8];
            #pragma unroll
            for (int nt = 0; nt < 8; nt++) {
                e[nt].x = ex2f(fmaf(m, c[nt][half * 2 + 0], cst));
                e[nt].y = ex2f(fmaf(m, c[nt][half * 2 + 1], cst));
            }
            float* orow = outb + (size_t)tout * P_NUM;
            #pragma unroll
            for (int j = 0; j < 4; j++) {
                const int nt0 = 2 * j, nt1 = 2 * j + 1;
                float2 send = (tq & 1) ? e[nt0] : e[nt1];
                long long sl; memcpy(&sl, &send, 8);
                long long rl = __shfl_xor_sync(0xffffffffu, sl, 1);
                float2 recv; memcpy(&recv, &rl, 8);
                float2 own = (tq & 1) ? e[nt1] : e[nt0];
                float4 v = (tq & 1)
                    ? make_float4(recv.x, recv.y, own.x, own.y)
                    : make_float4(own.x, own.y, recv.x, recv.y);
                const int col = ((tq & 1) ? nt1 : nt0) * 8 + (tq & 2) * 2;
                if (tout < T_LEN)
                    *reinterpret_cast<float4*>(orow + col) = v;
            }
        }
        // left pad rows [0,32): zeros (tile 0 only)
        if (blockIdx.x == 0) {
            float4 z = make_float4(0.f, 0.f, 0.f, 0.f);
            #pragma unroll
            for (int it = 0; it < 2; it++) {
                int qq  = tid + it * 256;
                int row = qq >> 4;
                int c4  = qq & 15;
                *reinterpret_cast<float4*>(outb + (size_t)row * P_NUM + c4 * 4) = z;
            }
        }
    }
}

extern "C" void kernel_launch(void* const* d_in, const int* in_sizes, int n_in,
                              void* d_out, int out_size) {
    const float* x  = (const float*)d_in[0];   // (32, 8192, 1)
    const float* sh = (const float*)d_in[1];   // (64, 1, 64)
    float* out = (float*)d_out;                // (32, 8192, 64)

    prep_kernel<<<N_STAT + 1, 320>>>(x, sh);

    cudaFuncSetAttribute(shapelet_hmma10_kernel,
                         cudaFuncAttributeMaxDynamicSharedMemorySize, DYN_SMEM);

    cudaLaunchAttribute attrs[1];
    attrs[0].id = cudaLaunchAttributeProgrammaticStreamSerialization;
    attrs[0].val.programmaticStreamSerializationAllowed = 1;

    cudaLaunchConfig_t cfg = {};
    cfg.gridDim  = dim3((TP_LEN + TILE_M - 1) / TILE_M, BS);   // (64, 32)
    cfg.blockDim = dim3(256, 1, 1);
    cfg.dynamicSmemBytes = DYN_SMEM;
    cfg.attrs    = attrs;
    cfg.numAttrs = 1;
    cudaLaunchKernelEx(&cfg, shapelet_hmma10_kernel, x, sh, out);
}